// round 14
// baseline (speedup 1.0000x reference)
#include <cuda_runtime.h>
#include <cuda_fp16.h>
#include <math.h>

#define NN 65536
#define EE 1048576
#define DD 512
#define BB 64
#define SL 16   // pool slices per batch
#define KS 4    // mlp k-splits

// ---------------- fp16x2 bit-cast helpers ----------------
__device__ __forceinline__ unsigned h2u(__half2 h) {
    union { __half2 h; unsigned u; } c; c.h = h; return c.u;
}
__device__ __forceinline__ __half2 u2h(unsigned u) {
    union { unsigned u; __half2 h; } c; c.u = u; return c.h;
}

// vectorized no-return atomic: one L2 op for both accumulators
__device__ __forceinline__ void red_add_v2(float* addr, float a, float b) {
    asm volatile("red.global.add.v2.f32 [%0], {%1, %2};"
                 :: "l"(addr), "f"(a), "f"(b) : "memory");
}

// ---------------- scratch (device globals; no allocations) ----------------
// dst-side hot record: qp gather + {s,t} reduction share one 32B sector.
// s at offset 8 keeps red.v2 8B-aligned.
struct __align__(16) DstE { float qp; float pad; float s; float t; };
__device__ DstE     g_dst[2][NN];
__device__ float2   g_kvt[2][NN];    // {kt, vt} packed src gather
__device__ float    g_score[2][NN];  // dense score stream
__device__ float    g_bsum[2][BB];
__device__ int      g_start[2][BB + 1];
__device__ __half   g_xn[2][NN * DD];    // fp16 LN output cache (128 MB)
__device__ float    g_padd[2][BB][SL][DD];
__device__ float    g_pmax[2][BB][SL][DD];
__device__ float    g_mpart[2][KS][BB][DD];

// ---------------- LayerNorm + kqv projection: 2 rows per warp --------------
// block = 256 threads = 8 warps = 16 rows; grid = (NN/16, 2)
__global__ void k_ln_kqv(const float* __restrict__ x0, const float* __restrict__ x1,
                         const float* __restrict__ g0, const float* __restrict__ g1,
                         const float* __restrict__ be0, const float* __restrict__ be1,
                         const float* __restrict__ W0, const float* __restrict__ W1,
                         const float* __restrict__ bk0, const float* __restrict__ bk1,
                         const float* __restrict__ krw, const float* __restrict__ krb,
                         const float* __restrict__ vrw, const float* __restrict__ vrb,
                         const float* __restrict__ prel) {
    int t = blockIdx.y;
    const float* x  = t ? x1 : x0;
    const float* g  = t ? g1 : g0;
    const float* be = t ? be1 : be0;
    const float* W  = t ? W1 : W0;
    const float* bk = t ? bk1 : bk0;

    __shared__ float sWT[3][DD];
    int tid = threadIdx.x;
    for (int i = tid; i < DD * 3; i += 256) sWT[i % 3][i / 3] = W[i];
    if (blockIdx.x == 0 && tid < BB) g_bsum[t][tid] = 0.f;  // zero batch sums
    __syncthreads();

    int warp = tid >> 5, lane = tid & 31;
    int row0 = blockIdx.x * 16 + warp * 2;
    int row1 = row0 + 1;

    const float4* xr0 = reinterpret_cast<const float4*>(x + (size_t)row0 * DD);
    const float4* xr1 = reinterpret_cast<const float4*>(x + (size_t)row1 * DD);
    float4 xa[4], xb[4];
    #pragma unroll
    for (int j = 0; j < 4; j++) xa[j] = xr0[lane + 32 * j];
    #pragma unroll
    for (int j = 0; j < 4; j++) xb[j] = xr1[lane + 32 * j];

    float sa = 0.f, ssa = 0.f, sb = 0.f, ssb = 0.f;
    #pragma unroll
    for (int j = 0; j < 4; j++) {
        sa  += xa[j].x + xa[j].y + xa[j].z + xa[j].w;
        ssa += xa[j].x * xa[j].x + xa[j].y * xa[j].y
             + xa[j].z * xa[j].z + xa[j].w * xa[j].w;
        sb  += xb[j].x + xb[j].y + xb[j].z + xb[j].w;
        ssb += xb[j].x * xb[j].x + xb[j].y * xb[j].y
             + xb[j].z * xb[j].z + xb[j].w * xb[j].w;
    }
    #pragma unroll
    for (int o = 16; o; o >>= 1) {
        sa  += __shfl_xor_sync(0xffffffffu, sa, o);
        ssa += __shfl_xor_sync(0xffffffffu, ssa, o);
        sb  += __shfl_xor_sync(0xffffffffu, sb, o);
        ssb += __shfl_xor_sync(0xffffffffu, ssb, o);
    }
    float ma = sa * (1.f / DD);
    float ra = rsqrtf(ssa * (1.f / DD) - ma * ma + 1e-5f);
    float mb = sb * (1.f / DD);
    float rb = rsqrtf(ssb * (1.f / DD) - mb * mb + 1e-5f);

    const float4* gr = reinterpret_cast<const float4*>(g);
    const float4* br = reinterpret_cast<const float4*>(be);
    const float4* w0p = reinterpret_cast<const float4*>(sWT[0]);
    const float4* w1p = reinterpret_cast<const float4*>(sWT[1]);
    const float4* w2p = reinterpret_cast<const float4*>(sWT[2]);
    uint2* xnp0 = reinterpret_cast<uint2*>(g_xn[t] + (size_t)row0 * DD);
    uint2* xnp1 = reinterpret_cast<uint2*>(g_xn[t] + (size_t)row1 * DD);

    float da0 = 0.f, da1 = 0.f, da2 = 0.f;
    float db0 = 0.f, db1 = 0.f, db2 = 0.f;
    #pragma unroll
    for (int j = 0; j < 4; j++) {
        int idx = lane + 32 * j;
        float4 gv = gr[idx], bv = br[idx];
        float4 w0 = w0p[idx], w1 = w1p[idx], w2 = w2p[idx];
        // row a
        float a0 = (xa[j].x - ma) * ra * gv.x + bv.x;
        float a1 = (xa[j].y - ma) * ra * gv.y + bv.y;
        float a2 = (xa[j].z - ma) * ra * gv.z + bv.z;
        float a3 = (xa[j].w - ma) * ra * gv.w + bv.w;
        uint2 pk;
        pk.x = h2u(__floats2half2_rn(a0, a1));
        pk.y = h2u(__floats2half2_rn(a2, a3));
        xnp0[idx] = pk;
        da0 += a0 * w0.x + a1 * w0.y + a2 * w0.z + a3 * w0.w;
        da1 += a0 * w1.x + a1 * w1.y + a2 * w1.z + a3 * w1.w;
        da2 += a0 * w2.x + a1 * w2.y + a2 * w2.z + a3 * w2.w;
        // row b
        float b0 = (xb[j].x - mb) * rb * gv.x + bv.x;
        float b1 = (xb[j].y - mb) * rb * gv.y + bv.y;
        float b2 = (xb[j].z - mb) * rb * gv.z + bv.z;
        float b3 = (xb[j].w - mb) * rb * gv.w + bv.w;
        pk.x = h2u(__floats2half2_rn(b0, b1));
        pk.y = h2u(__floats2half2_rn(b2, b3));
        xnp1[idx] = pk;
        db0 += b0 * w0.x + b1 * w0.y + b2 * w0.z + b3 * w0.w;
        db1 += b0 * w1.x + b1 * w1.y + b2 * w1.z + b3 * w1.w;
        db2 += b0 * w2.x + b1 * w2.y + b2 * w2.z + b3 * w2.w;
    }
    #pragma unroll
    for (int o = 16; o; o >>= 1) {
        da0 += __shfl_xor_sync(0xffffffffu, da0, o);
        da1 += __shfl_xor_sync(0xffffffffu, da1, o);
        da2 += __shfl_xor_sync(0xffffffffu, da2, o);
        db0 += __shfl_xor_sync(0xffffffffu, db0, o);
        db1 += __shfl_xor_sync(0xffffffffu, db1, o);
        db2 += __shfl_xor_sync(0xffffffffu, db2, o);
    }
    if (lane == 0) {
        float kw = krw[t], kb = krb[t], vw = vrw[t], vb = vrb[t], pr = prel[1 - t];
        float bk0v = bk[0], bk1v = bk[1], bk2v = bk[2];
        g_kvt[t][row0] = make_float2((da0 + bk0v) * kw + kb, (da2 + bk2v) * vw + vb);
        g_kvt[t][row1] = make_float2((db0 + bk0v) * kw + kb, (db2 + bk2v) * vw + vb);
        DstE d0r; d0r.qp = (da1 + bk1v) * pr; d0r.pad = 0.f; d0r.s = 0.f; d0r.t = 0.f;
        DstE d1r; d1r.qp = (db1 + bk1v) * pr; d1r.pad = 0.f; d1r.s = 0.f; d1r.t = 0.f;
        g_dst[t][row0] = d0r;
        g_dst[t][row1] = d1r;
    }
}

// ---------------- edge attention: dst gather + red share one sector --------
// grid (EE/1024, 2); 4 edges/thread via int4
__global__ void k_edge(const int* __restrict__ ei0, const int* __restrict__ ei1) {
    int dir = blockIdx.y;
    const int* ei = dir ? ei1 : ei0;
    int ts = dir, td = 1 - dir;
    int e4 = blockIdx.x * 256 + threadIdx.x;
    int4 s4 = reinterpret_cast<const int4*>(ei)[e4];
    int4 d4 = reinterpret_cast<const int4*>(ei + EE)[e4];
    {
        float2 kv = g_kvt[ts][s4.x];
        DstE* dp = &g_dst[td][d4.x];
        float ex = __expf(dp->qp * kv.x);
        red_add_v2(&dp->s, ex, ex * kv.y);
    }
    {
        float2 kv = g_kvt[ts][s4.y];
        DstE* dp = &g_dst[td][d4.y];
        float ex = __expf(dp->qp * kv.x);
        red_add_v2(&dp->s, ex, ex * kv.y);
    }
    {
        float2 kv = g_kvt[ts][s4.z];
        DstE* dp = &g_dst[td][d4.z];
        float ex = __expf(dp->qp * kv.x);
        red_add_v2(&dp->s, ex, ex * kv.y);
    }
    {
        float2 kv = g_kvt[ts][s4.w];
        DstE* dp = &g_dst[td][d4.w];
        float ex = __expf(dp->qp * kv.x);
        red_add_v2(&dp->s, ex, ex * kv.y);
    }
}

// ---------------- score = gelu(aggr*w+b); bsum; segment starts -------------
__global__ void k_score(const float* __restrict__ w0, const float* __restrict__ bo0,
                        const float* __restrict__ w1, const float* __restrict__ bo1,
                        const int* __restrict__ batch0, const int* __restrict__ batch1) {
    int t = blockIdx.y;
    const float* wout = t ? w1 : w0;
    const float* bout = t ? bo1 : bo0;
    const int* batch  = t ? batch1 : batch0;
    int n = blockIdx.x * 256 + threadIdx.x;

    int b = batch[n];
    // --- segment starts (batch is sorted) ---
    int prev = (n == 0) ? -1 : batch[n - 1];
    for (int bb = prev + 1; bb <= b; bb++) g_start[t][bb] = n;
    if (n == NN - 1) {
        for (int bb = b + 1; bb <= BB; bb++) g_start[t][bb] = NN;
    }

    float4 dr = *reinterpret_cast<const float4*>(&g_dst[t][n]);  // {qp,pad,s,t}
    float aggr = (dr.z > 0.f) ? dr.w / dr.z : 0.f;
    float xx = aggr * wout[0] + bout[0];
    float sc = 0.5f * xx * (1.f + erff(xx * 0.7071067811865475f));
    g_score[t][n] = sc;
    float ev = __expf(sc);
    int b0 = __shfl_sync(0xffffffffu, b, 0);
    if (__all_sync(0xffffffffu, b == b0)) {
        float sv = ev;
        #pragma unroll
        for (int o = 16; o; o >>= 1) sv += __shfl_xor_sync(0xffffffffu, sv, o);
        if ((threadIdx.x & 31) == 0) atomicAdd(&g_bsum[t][b], sv);
    } else {
        atomicAdd(&g_bsum[t][b], ev);
    }
}

// ---------------- pooling partials from fp16 xn; sn staged in smem ---------
// grid (BB*SL, 2), 128 thr, 4 cols each, 8-row unroll  (measured-best, frozen)
__global__ void k_pool() {
    __shared__ float sn_s[256];
    int t  = blockIdx.y;
    int b  = blockIdx.x >> 4;
    int sl = blockIdx.x & (SL - 1);
    int tid = threadIdx.x;

    int s0 = g_start[t][b], s1 = g_start[t][b + 1];
    float bsinv = 1.f / g_bsum[t][b];
    int len = s1 - s0;
    int ps  = (len + SL - 1) / SL;
    int r0  = s0 + sl * ps;
    int r1  = min(r0 + ps, s1);
    int cnt = max(r1 - r0, 0);

    // compute sn once per node (cooperative), then broadcast from smem
    for (int i = tid; i < cnt; i += 128)
        sn_s[i] = __expf(g_score[t][r0 + i]) * bsinv;
    __syncthreads();

    float4 acc = make_float4(0.f, 0.f, 0.f, 0.f);
    float4 mx  = make_float4(-INFINITY, -INFINITY, -INFINITY, -INFINITY);
    const uint2* xn4 = reinterpret_cast<const uint2*>(g_xn[t]);

    int n = 0;
    for (; n + 8 <= cnt; n += 8) {
        uint2 pk[8];
        #pragma unroll
        for (int u = 0; u < 8; u++) pk[u] = xn4[(size_t)(r0 + n + u) * 128 + tid];
        #pragma unroll
        for (int u = 0; u < 8; u++) {
            float sn = sn_s[n + u];
            float2 lo = __half22float2(u2h(pk[u].x));
            float2 hi = __half22float2(u2h(pk[u].y));
            float w0 = lo.x * sn, w1 = lo.y * sn;
            float w2 = hi.x * sn, w3 = hi.y * sn;
            acc.x += w0; acc.y += w1; acc.z += w2; acc.w += w3;
            mx.x = fmaxf(mx.x, w0); mx.y = fmaxf(mx.y, w1);
            mx.z = fmaxf(mx.z, w2); mx.w = fmaxf(mx.w, w3);
        }
    }
    for (; n < cnt; n++) {
        uint2 pk = xn4[(size_t)(r0 + n) * 128 + tid];
        float sn = sn_s[n];
        float2 lo = __half22float2(u2h(pk.x));
        float2 hi = __half22float2(u2h(pk.y));
        float w0 = lo.x * sn, w1 = lo.y * sn;
        float w2 = hi.x * sn, w3 = hi.y * sn;
        acc.x += w0; acc.y += w1; acc.z += w2; acc.w += w3;
        mx.x = fmaxf(mx.x, w0); mx.y = fmaxf(mx.y, w1);
        mx.z = fmaxf(mx.z, w2); mx.w = fmaxf(mx.w, w3);
    }
    reinterpret_cast<float4*>(g_padd[t][b][sl])[tid] = acc;
    reinterpret_cast<float4*>(g_pmax[t][b][sl])[tid] = mx;
}

// ---------------- MLP partial with inline slice combine --------------------
// grid (4 colchunks, 8 bgroups, 2*KS)
__global__ void k_mlp(const float* __restrict__ W0, const float* __restrict__ W1) {
    __shared__ float cat[8][256];
    int dchunk = blockIdx.x, bg = blockIdx.y;
    int t  = blockIdx.z >> 2;
    int ks = blockIdx.z & 3;
    const float* W = t ? W1 : W0;
    bool is_add = (ks < 2);
    int koff = (ks & 1) * 256;
    int tid = threadIdx.x;

    // combine SL slice partials inline while filling smem
    for (int i = tid; i < 8 * 256; i += 128) {
        int bb = i >> 8, k = i & 255;
        int gb = bg * 8 + bb;
        float v;
        if (is_add) {
            v = 0.f;
            #pragma unroll
            for (int s = 0; s < SL; s++) v += g_padd[t][gb][s][koff + k];
        } else {
            v = -INFINITY;
            #pragma unroll
            for (int s = 0; s < SL; s++) v = fmaxf(v, g_pmax[t][gb][s][koff + k]);
        }
        cat[bb][k] = v;
    }
    __syncthreads();

    int col = dchunk * 128 + tid;
    int kbase = ks * 256;
    float acc[8];
    #pragma unroll
    for (int bb = 0; bb < 8; bb++) acc[bb] = 0.f;

    for (int k = 0; k < 256; k += 4) {
        float w0 = W[(size_t)(kbase + k + 0) * DD + col];
        float w1 = W[(size_t)(kbase + k + 1) * DD + col];
        float w2 = W[(size_t)(kbase + k + 2) * DD + col];
        float w3 = W[(size_t)(kbase + k + 3) * DD + col];
        #pragma unroll
        for (int bb = 0; bb < 8; bb++) {
            const float4 c = reinterpret_cast<const float4*>(cat[bb])[k >> 2];
            acc[bb] += c.x * w0 + c.y * w1 + c.z * w2 + c.w * w3;
        }
    }
    #pragma unroll
    for (int bb = 0; bb < 8; bb++)
        g_mpart[t][ks][bg * 8 + bb][col] = acc[bb];
}

// ---------------- final combine + bias ---------------------------------------
__global__ void k_out(const float* __restrict__ bmlp0,
                      const float* __restrict__ bmlp1,
                      float* __restrict__ out) {
    int b = blockIdx.x, t = blockIdx.y;
    int col = threadIdx.x;
    const float* bias = t ? bmlp1 : bmlp0;
    float v = bias[col];
    #pragma unroll
    for (int ks = 0; ks < KS; ks++) v += g_mpart[t][ks][b][col];
    out[b * (2 * DD) + t * DD + col] = v;
}

// ---------------- launch -----------------------------------------------------
extern "C" void kernel_launch(void* const* d_in, const int* in_sizes, int n_in,
                              void* d_out, int out_size) {
    const float* x_inst     = (const float*)d_in[0];
    const float* x_net      = (const float*)d_in[1];
    const float* ln_g_inst  = (const float*)d_in[2];
    const float* ln_b_inst  = (const float*)d_in[3];
    const float* ln_g_net   = (const float*)d_in[4];
    const float* ln_b_net   = (const float*)d_in[5];
    const float* Wkqv_inst  = (const float*)d_in[6];
    const float* bkqv_inst  = (const float*)d_in[7];
    const float* Wkqv_net   = (const float*)d_in[8];
    const float* bkqv_net   = (const float*)d_in[9];
    const float* k_rel_w    = (const float*)d_in[10];
    const float* k_rel_b    = (const float*)d_in[11];
    const float* v_rel_w    = (const float*)d_in[12];
    const float* v_rel_b    = (const float*)d_in[13];
    const float* p_rel      = (const float*)d_in[14];
    const float* w_out_inst = (const float*)d_in[15];
    const float* b_out_inst = (const float*)d_in[16];
    const float* w_out_net  = (const float*)d_in[17];
    const float* b_out_net  = (const float*)d_in[18];
    const float* W_mlp_inst = (const float*)d_in[19];
    const float* b_mlp_inst = (const float*)d_in[20];
    const float* W_mlp_net  = (const float*)d_in[21];
    const float* b_mlp_net  = (const float*)d_in[22];
    const int*   ei_i2n     = (const int*)d_in[23];
    const int*   ei_n2i     = (const int*)d_in[24];
    const int*   batch_inst = (const int*)d_in[25];
    const int*   batch_net  = (const int*)d_in[26];
    float* out = (float*)d_out;

    k_ln_kqv<<<dim3(NN / 16, 2), 256>>>(x_inst, x_net, ln_g_inst, ln_g_net,
                                        ln_b_inst, ln_b_net, Wkqv_inst, Wkqv_net,
                                        bkqv_inst, bkqv_net,
                                        k_rel_w, k_rel_b, v_rel_w, v_rel_b, p_rel);
    k_edge<<<dim3(EE / 1024, 2), 256>>>(ei_i2n, ei_n2i);
    k_score<<<dim3(NN / 256, 2), 256>>>(w_out_inst, b_out_inst, w_out_net, b_out_net,
                                        batch_inst, batch_net);
    k_pool<<<dim3(BB * SL, 2), 128>>>();
    k_mlp<<<dim3(4, 8, 2 * KS), 128>>>(W_mlp_inst, W_mlp_net);
    k_out<<<dim3(BB, 2), 512>>>(b_mlp_inst, b_mlp_net, out);
}

// round 15
// speedup vs baseline: 1.0444x; 1.0444x over previous
#include <cuda_runtime.h>
#include <cuda_fp16.h>
#include <math.h>

#define NN 65536
#define EE 1048576
#define DD 512
#define BB 64
#define SL 16   // pool slices per batch
#define KS 4    // mlp k-splits

// ---------------- fp16x2 bit-cast helpers ----------------
__device__ __forceinline__ unsigned h2u(__half2 h) {
    union { __half2 h; unsigned u; } c; c.h = h; return c.u;
}
__device__ __forceinline__ __half2 u2h(unsigned u) {
    union { unsigned u; __half2 h; } c; c.u = u; return c.h;
}

// vectorized no-return atomic: one L2 op for both accumulators
__device__ __forceinline__ void red_add_v2(float2* addr, float a, float b) {
    asm volatile("red.global.add.v2.f32 [%0], {%1, %2};"
                 :: "l"(addr), "f"(a), "f"(b) : "memory");
}

// ---------------- scratch (device globals; no allocations) ----------------
__device__ float2   g_kvt[2][NN];    // {kt, vt} packed src gather
__device__ float    g_qp[2][NN];     // q * p_rel[rel_dst] (dense 4B gather)
__device__ float2   g_st[2][NN];     // {sum exp, sum exp*vt} single red.v2 target
__device__ float    g_score[2][NN];  // dense score stream
__device__ float    g_bsum[2][BB];
__device__ int      g_start[2][BB + 1];
__device__ __half   g_xn[2][NN * DD];    // fp16 LN output cache (128 MB)
__device__ float    g_padd[2][BB][SL][DD];
__device__ float    g_pmax[2][BB][SL][DD];

// ---------------- LayerNorm + kqv projection: 2 rows per warp --------------
// block = 256 threads = 8 warps = 16 rows; grid = (NN/16, 2)
__global__ void k_ln_kqv(const float* __restrict__ x0, const float* __restrict__ x1,
                         const float* __restrict__ g0, const float* __restrict__ g1,
                         const float* __restrict__ be0, const float* __restrict__ be1,
                         const float* __restrict__ W0, const float* __restrict__ W1,
                         const float* __restrict__ bk0, const float* __restrict__ bk1,
                         const float* __restrict__ krw, const float* __restrict__ krb,
                         const float* __restrict__ vrw, const float* __restrict__ vrb,
                         const float* __restrict__ prel) {
    int t = blockIdx.y;
    const float* x  = t ? x1 : x0;
    const float* g  = t ? g1 : g0;
    const float* be = t ? be1 : be0;
    const float* W  = t ? W1 : W0;
    const float* bk = t ? bk1 : bk0;

    __shared__ float sWT[3][DD];
    int tid = threadIdx.x;
    for (int i = tid; i < DD * 3; i += 256) sWT[i % 3][i / 3] = W[i];
    if (blockIdx.x == 0 && tid < BB) g_bsum[t][tid] = 0.f;  // zero batch sums
    __syncthreads();

    int warp = tid >> 5, lane = tid & 31;
    int row0 = blockIdx.x * 16 + warp * 2;
    int row1 = row0 + 1;

    const float4* xr0 = reinterpret_cast<const float4*>(x + (size_t)row0 * DD);
    const float4* xr1 = reinterpret_cast<const float4*>(x + (size_t)row1 * DD);
    float4 xa[4], xb[4];
    #pragma unroll
    for (int j = 0; j < 4; j++) xa[j] = xr0[lane + 32 * j];
    #pragma unroll
    for (int j = 0; j < 4; j++) xb[j] = xr1[lane + 32 * j];

    float sa = 0.f, ssa = 0.f, sb = 0.f, ssb = 0.f;
    #pragma unroll
    for (int j = 0; j < 4; j++) {
        sa  += xa[j].x + xa[j].y + xa[j].z + xa[j].w;
        ssa += xa[j].x * xa[j].x + xa[j].y * xa[j].y
             + xa[j].z * xa[j].z + xa[j].w * xa[j].w;
        sb  += xb[j].x + xb[j].y + xb[j].z + xb[j].w;
        ssb += xb[j].x * xb[j].x + xb[j].y * xb[j].y
             + xb[j].z * xb[j].z + xb[j].w * xb[j].w;
    }
    #pragma unroll
    for (int o = 16; o; o >>= 1) {
        sa  += __shfl_xor_sync(0xffffffffu, sa, o);
        ssa += __shfl_xor_sync(0xffffffffu, ssa, o);
        sb  += __shfl_xor_sync(0xffffffffu, sb, o);
        ssb += __shfl_xor_sync(0xffffffffu, ssb, o);
    }
    float ma = sa * (1.f / DD);
    float ra = rsqrtf(ssa * (1.f / DD) - ma * ma + 1e-5f);
    float mb = sb * (1.f / DD);
    float rb = rsqrtf(ssb * (1.f / DD) - mb * mb + 1e-5f);

    const float4* gr = reinterpret_cast<const float4*>(g);
    const float4* br = reinterpret_cast<const float4*>(be);
    const float4* w0p = reinterpret_cast<const float4*>(sWT[0]);
    const float4* w1p = reinterpret_cast<const float4*>(sWT[1]);
    const float4* w2p = reinterpret_cast<const float4*>(sWT[2]);
    uint2* xnp0 = reinterpret_cast<uint2*>(g_xn[t] + (size_t)row0 * DD);
    uint2* xnp1 = reinterpret_cast<uint2*>(g_xn[t] + (size_t)row1 * DD);

    float da0 = 0.f, da1 = 0.f, da2 = 0.f;
    float db0 = 0.f, db1 = 0.f, db2 = 0.f;
    #pragma unroll
    for (int j = 0; j < 4; j++) {
        int idx = lane + 32 * j;
        float4 gv = gr[idx], bv = br[idx];
        float4 w0 = w0p[idx], w1 = w1p[idx], w2 = w2p[idx];
        // row a
        float a0 = (xa[j].x - ma) * ra * gv.x + bv.x;
        float a1 = (xa[j].y - ma) * ra * gv.y + bv.y;
        float a2 = (xa[j].z - ma) * ra * gv.z + bv.z;
        float a3 = (xa[j].w - ma) * ra * gv.w + bv.w;
        uint2 pk;
        pk.x = h2u(__floats2half2_rn(a0, a1));
        pk.y = h2u(__floats2half2_rn(a2, a3));
        xnp0[idx] = pk;
        da0 += a0 * w0.x + a1 * w0.y + a2 * w0.z + a3 * w0.w;
        da1 += a0 * w1.x + a1 * w1.y + a2 * w1.z + a3 * w1.w;
        da2 += a0 * w2.x + a1 * w2.y + a2 * w2.z + a3 * w2.w;
        // row b
        float b0 = (xb[j].x - mb) * rb * gv.x + bv.x;
        float b1 = (xb[j].y - mb) * rb * gv.y + bv.y;
        float b2 = (xb[j].z - mb) * rb * gv.z + bv.z;
        float b3 = (xb[j].w - mb) * rb * gv.w + bv.w;
        pk.x = h2u(__floats2half2_rn(b0, b1));
        pk.y = h2u(__floats2half2_rn(b2, b3));
        xnp1[idx] = pk;
        db0 += b0 * w0.x + b1 * w0.y + b2 * w0.z + b3 * w0.w;
        db1 += b0 * w1.x + b1 * w1.y + b2 * w1.z + b3 * w1.w;
        db2 += b0 * w2.x + b1 * w2.y + b2 * w2.z + b3 * w2.w;
    }
    #pragma unroll
    for (int o = 16; o; o >>= 1) {
        da0 += __shfl_xor_sync(0xffffffffu, da0, o);
        da1 += __shfl_xor_sync(0xffffffffu, da1, o);
        da2 += __shfl_xor_sync(0xffffffffu, da2, o);
        db0 += __shfl_xor_sync(0xffffffffu, db0, o);
        db1 += __shfl_xor_sync(0xffffffffu, db1, o);
        db2 += __shfl_xor_sync(0xffffffffu, db2, o);
    }
    if (lane == 0) {
        float kw = krw[t], kb = krb[t], vw = vrw[t], vb = vrb[t], pr = prel[1 - t];
        float bk0v = bk[0], bk1v = bk[1], bk2v = bk[2];
        g_kvt[t][row0] = make_float2((da0 + bk0v) * kw + kb, (da2 + bk2v) * vw + vb);
        g_qp[t][row0]  = (da1 + bk1v) * pr;
        g_st[t][row0]  = make_float2(0.f, 0.f);
        g_kvt[t][row1] = make_float2((db0 + bk0v) * kw + kb, (db2 + bk2v) * vw + vb);
        g_qp[t][row1]  = (db1 + bk1v) * pr;
        g_st[t][row1]  = make_float2(0.f, 0.f);
    }
}

// ---------------- edge attention: fused dirs, single red.v2 per edge -------
// grid (EE/1024, 2); 4 edges/thread via int4
__global__ void k_edge(const int* __restrict__ ei0, const int* __restrict__ ei1) {
    int dir = blockIdx.y;
    const int* ei = dir ? ei1 : ei0;
    int ts = dir, td = 1 - dir;
    int e4 = blockIdx.x * 256 + threadIdx.x;
    int4 s4 = reinterpret_cast<const int4*>(ei)[e4];
    int4 d4 = reinterpret_cast<const int4*>(ei + EE)[e4];
    {
        float2 kv = g_kvt[ts][s4.x];
        float ex = __expf(g_qp[td][d4.x] * kv.x);
        red_add_v2(&g_st[td][d4.x], ex, ex * kv.y);
    }
    {
        float2 kv = g_kvt[ts][s4.y];
        float ex = __expf(g_qp[td][d4.y] * kv.x);
        red_add_v2(&g_st[td][d4.y], ex, ex * kv.y);
    }
    {
        float2 kv = g_kvt[ts][s4.z];
        float ex = __expf(g_qp[td][d4.z] * kv.x);
        red_add_v2(&g_st[td][d4.z], ex, ex * kv.y);
    }
    {
        float2 kv = g_kvt[ts][s4.w];
        float ex = __expf(g_qp[td][d4.w] * kv.x);
        red_add_v2(&g_st[td][d4.w], ex, ex * kv.y);
    }
}

// ---------------- score = gelu(aggr*w+b); bsum; segment starts -------------
__global__ void k_score(const float* __restrict__ w0, const float* __restrict__ bo0,
                        const float* __restrict__ w1, const float* __restrict__ bo1,
                        const int* __restrict__ batch0, const int* __restrict__ batch1) {
    int t = blockIdx.y;
    const float* wout = t ? w1 : w0;
    const float* bout = t ? bo1 : bo0;
    const int* batch  = t ? batch1 : batch0;
    int n = blockIdx.x * 256 + threadIdx.x;

    int b = batch[n];
    // --- segment starts (batch is sorted) ---
    int prev = (n == 0) ? -1 : batch[n - 1];
    for (int bb = prev + 1; bb <= b; bb++) g_start[t][bb] = n;
    if (n == NN - 1) {
        for (int bb = b + 1; bb <= BB; bb++) g_start[t][bb] = NN;
    }

    float2 st = g_st[t][n];
    float aggr = (st.x > 0.f) ? st.y / st.x : 0.f;
    float xx = aggr * wout[0] + bout[0];
    float sc = 0.5f * xx * (1.f + erff(xx * 0.7071067811865475f));
    g_score[t][n] = sc;
    float ev = __expf(sc);
    int b0 = __shfl_sync(0xffffffffu, b, 0);
    if (__all_sync(0xffffffffu, b == b0)) {
        float sv = ev;
        #pragma unroll
        for (int o = 16; o; o >>= 1) sv += __shfl_xor_sync(0xffffffffu, sv, o);
        if ((threadIdx.x & 31) == 0) atomicAdd(&g_bsum[t][b], sv);
    } else {
        atomicAdd(&g_bsum[t][b], ev);
    }
}

// ---------------- pooling partials from fp16 xn; sn staged in smem ---------
// grid (BB*SL, 2), 128 thr, 4 cols each, 8-row unroll  (measured-best, frozen)
// sl==0 blocks also seed `out` with the MLP bias (k_mlp accumulates on top)
__global__ void k_pool(const float* __restrict__ bmlp0,
                       const float* __restrict__ bmlp1,
                       float* __restrict__ out) {
    __shared__ float sn_s[256];
    int t  = blockIdx.y;
    int b  = blockIdx.x >> 4;
    int sl = blockIdx.x & (SL - 1);
    int tid = threadIdx.x;

    if (sl == 0) {
        const float* bias = t ? bmlp1 : bmlp0;
        const float4* b4 = reinterpret_cast<const float4*>(bias);
        float4* o4 = reinterpret_cast<float4*>(out + (size_t)b * (2 * DD) + t * DD);
        o4[tid] = b4[tid];
    }

    int s0 = g_start[t][b], s1 = g_start[t][b + 1];
    float bsinv = 1.f / g_bsum[t][b];
    int len = s1 - s0;
    int ps  = (len + SL - 1) / SL;
    int r0  = s0 + sl * ps;
    int r1  = min(r0 + ps, s1);
    int cnt = max(r1 - r0, 0);

    // compute sn once per node (cooperative), then broadcast from smem
    for (int i = tid; i < cnt; i += 128)
        sn_s[i] = __expf(g_score[t][r0 + i]) * bsinv;
    __syncthreads();

    float4 acc = make_float4(0.f, 0.f, 0.f, 0.f);
    float4 mx  = make_float4(-INFINITY, -INFINITY, -INFINITY, -INFINITY);
    const uint2* xn4 = reinterpret_cast<const uint2*>(g_xn[t]);

    int n = 0;
    for (; n + 8 <= cnt; n += 8) {
        uint2 pk[8];
        #pragma unroll
        for (int u = 0; u < 8; u++) pk[u] = xn4[(size_t)(r0 + n + u) * 128 + tid];
        #pragma unroll
        for (int u = 0; u < 8; u++) {
            float sn = sn_s[n + u];
            float2 lo = __half22float2(u2h(pk[u].x));
            float2 hi = __half22float2(u2h(pk[u].y));
            float w0 = lo.x * sn, w1 = lo.y * sn;
            float w2 = hi.x * sn, w3 = hi.y * sn;
            acc.x += w0; acc.y += w1; acc.z += w2; acc.w += w3;
            mx.x = fmaxf(mx.x, w0); mx.y = fmaxf(mx.y, w1);
            mx.z = fmaxf(mx.z, w2); mx.w = fmaxf(mx.w, w3);
        }
    }
    for (; n < cnt; n++) {
        uint2 pk = xn4[(size_t)(r0 + n) * 128 + tid];
        float sn = sn_s[n];
        float2 lo = __half22float2(u2h(pk.x));
        float2 hi = __half22float2(u2h(pk.y));
        float w0 = lo.x * sn, w1 = lo.y * sn;
        float w2 = hi.x * sn, w3 = hi.y * sn;
        acc.x += w0; acc.y += w1; acc.z += w2; acc.w += w3;
        mx.x = fmaxf(mx.x, w0); mx.y = fmaxf(mx.y, w1);
        mx.z = fmaxf(mx.z, w2); mx.w = fmaxf(mx.w, w3);
    }
    reinterpret_cast<float4*>(g_padd[t][b][sl])[tid] = acc;
    reinterpret_cast<float4*>(g_pmax[t][b][sl])[tid] = mx;
}

// ---------------- MLP partial: inline slice combine, red直接 into out ------
// grid (4 colchunks, 8 bgroups, 2*KS)
__global__ void k_mlp(const float* __restrict__ W0, const float* __restrict__ W1,
                      float* __restrict__ out) {
    __shared__ float cat[8][256];
    int dchunk = blockIdx.x, bg = blockIdx.y;
    int t  = blockIdx.z >> 2;
    int ks = blockIdx.z & 3;
    const float* W = t ? W1 : W0;
    bool is_add = (ks < 2);
    int koff = (ks & 1) * 256;
    int tid = threadIdx.x;

    // combine SL slice partials inline while filling smem
    for (int i = tid; i < 8 * 256; i += 128) {
        int bb = i >> 8, k = i & 255;
        int gb = bg * 8 + bb;
        float v;
        if (is_add) {
            v = 0.f;
            #pragma unroll
            for (int s = 0; s < SL; s++) v += g_padd[t][gb][s][koff + k];
        } else {
            v = -INFINITY;
            #pragma unroll
            for (int s = 0; s < SL; s++) v = fmaxf(v, g_pmax[t][gb][s][koff + k]);
        }
        cat[bb][k] = v;
    }
    __syncthreads();

    int col = dchunk * 128 + tid;
    int kbase = ks * 256;
    float acc[8];
    #pragma unroll
    for (int bb = 0; bb < 8; bb++) acc[bb] = 0.f;

    for (int k = 0; k < 256; k += 4) {
        float w0 = W[(size_t)(kbase + k + 0) * DD + col];
        float w1 = W[(size_t)(kbase + k + 1) * DD + col];
        float w2 = W[(size_t)(kbase + k + 2) * DD + col];
        float w3 = W[(size_t)(kbase + k + 3) * DD + col];
        #pragma unroll
        for (int bb = 0; bb < 8; bb++) {
            const float4 c = reinterpret_cast<const float4*>(cat[bb])[k >> 2];
            acc[bb] += c.x * w0 + c.y * w1 + c.z * w2 + c.w * w3;
        }
    }
    #pragma unroll
    for (int bb = 0; bb < 8; bb++) {
        int gb = bg * 8 + bb;
        atomicAdd(&out[(size_t)gb * (2 * DD) + t * DD + col], acc[bb]);
    }
}

// ---------------- launch -----------------------------------------------------
extern "C" void kernel_launch(void* const* d_in, const int* in_sizes, int n_in,
                              void* d_out, int out_size) {
    const float* x_inst     = (const float*)d_in[0];
    const float* x_net      = (const float*)d_in[1];
    const float* ln_g_inst  = (const float*)d_in[2];
    const float* ln_b_inst  = (const float*)d_in[3];
    const float* ln_g_net   = (const float*)d_in[4];
    const float* ln_b_net   = (const float*)d_in[5];
    const float* Wkqv_inst  = (const float*)d_in[6];
    const float* bkqv_inst  = (const float*)d_in[7];
    const float* Wkqv_net   = (const float*)d_in[8];
    const float* bkqv_net   = (const float*)d_in[9];
    const float* k_rel_w    = (const float*)d_in[10];
    const float* k_rel_b    = (const float*)d_in[11];
    const float* v_rel_w    = (const float*)d_in[12];
    const float* v_rel_b    = (const float*)d_in[13];
    const float* p_rel      = (const float*)d_in[14];
    const float* w_out_inst = (const float*)d_in[15];
    const float* b_out_inst = (const float*)d_in[16];
    const float* w_out_net  = (const float*)d_in[17];
    const float* b_out_net  = (const float*)d_in[18];
    const float* W_mlp_inst = (const float*)d_in[19];
    const float* b_mlp_inst = (const float*)d_in[20];
    const float* W_mlp_net  = (const float*)d_in[21];
    const float* b_mlp_net  = (const float*)d_in[22];
    const int*   ei_i2n     = (const int*)d_in[23];
    const int*   ei_n2i     = (const int*)d_in[24];
    const int*   batch_inst = (const int*)d_in[25];
    const int*   batch_net  = (const int*)d_in[26];
    float* out = (float*)d_out;

    k_ln_kqv<<<dim3(NN / 16, 2), 256>>>(x_inst, x_net, ln_g_inst, ln_g_net,
                                        ln_b_inst, ln_b_net, Wkqv_inst, Wkqv_net,
                                        bkqv_inst, bkqv_net,
                                        k_rel_w, k_rel_b, v_rel_w, v_rel_b, p_rel);
    k_edge<<<dim3(EE / 1024, 2), 256>>>(ei_i2n, ei_n2i);
    k_score<<<dim3(NN / 256, 2), 256>>>(w_out_inst, b_out_inst, w_out_net, b_out_net,
                                        batch_inst, batch_net);
    k_pool<<<dim3(BB * SL, 2), 128>>>(b_mlp_inst, b_mlp_net, out);
    k_mlp<<<dim3(4, 8, 2 * KS), 128>>>(W_mlp_inst, W_mlp_net, out);
}